// round 17
// baseline (speedup 1.0000x reference)
#include <cuda_runtime.h>

typedef unsigned long long u64;
struct uu2 { u64 a, b; };

// ---------------- merged constant blob (written DIRECTLY by repack kernel) ----------------
// linsp: [r*24+o] = (Wl[o][f(r)], same) splatted, r = t2*16+ch, f = ch*6+t2 ; then 24 splatted bl
// pack:  [0..256)    wino12[(ci*4+m)*8+co]        (Winograd-transformed conv12 weights)
//        [256..640)  w21p[(ci*3+k)*16+co]         (classic conv21 weights)
//        [640..1664) wino22[(ci*4+m)*16+co]       (Winograd-transformed conv22 weights)
//        [3648..3672) w11p[k*8+co] | [3672..3680) b11 | [3680..3688) b12
//        [3688..3704) b21 | [3704..3720) b22 | [3720..3744) bl
#define LINW (96 * 24)
#define PACKN 3744
struct __align__(16) Blob {
    u64   linsp[LINW + 24];
    float pack[PACKN];
};
__constant__ Blob c_blob;

// p2 scratch [feature r][sample]
#define MAXN 131072
__device__ float g_p2[96 * MAXN];

__device__ __forceinline__ u64 pk2(float lo, float hi) {
    u64 r; asm("mov.b64 %0,{%1,%2};" : "=l"(r) : "f"(lo), "f"(hi)); return r;
}
__device__ __forceinline__ float2 upk2(u64 v) {
    float2 f; asm("mov.b64 {%0,%1},%2;" : "=f"(f.x), "=f"(f.y) : "l"(v)); return f;
}
__device__ __forceinline__ u64 ffma2(u64 a, u64 b, u64 c) {
    u64 d; asm("fma.rn.f32x2 %0,%1,%2,%3;" : "=l"(d) : "l"(a), "l"(b), "l"(c)); return d;
}
__device__ __forceinline__ u64 add2(u64 a, u64 b) {
    u64 d; asm("add.rn.f32x2 %0,%1,%2;" : "=l"(d) : "l"(a), "l"(b)); return d;
}
__device__ __forceinline__ u64 neg2(u64 a) {            // packed sign flip (alu pipe)
    return a ^ 0x8000000080000000ull;
}
__device__ __forceinline__ uu2 cpk4(int idx) {          // LDC.128 from pack (idx mult of 4)
    ulonglong2 v = *reinterpret_cast<const ulonglong2*>(&c_blob.pack[idx]);
    uu2 r; r.a = v.x; r.b = v.y; return r;
}

// Winograd F(2,3) weight transform: m0=w0, m1=(w0+w1+w2)/2, m2=(w0-w1+w2)/2, m3=w2
__device__ __forceinline__ float wino_w(float w0, float w1, float w2, int m) {
    if (m == 0) return w0;
    if (m == 1) return 0.5f * (w0 + w1 + w2);
    if (m == 2) return 0.5f * (w0 - w1 + w2);
    return w2;
}

// writes straight into the constant bank's backing store
__global__ void repack_kernel(Blob* __restrict__ dst,
    const float* __restrict__ w11, const float* __restrict__ b11,
    const float* __restrict__ w12, const float* __restrict__ b12,
    const float* __restrict__ w21, const float* __restrict__ b21,
    const float* __restrict__ w22, const float* __restrict__ b22,
    const float* __restrict__ Wl,  const float* __restrict__ bl)
{
    int gtid = blockIdx.x * 128 + threadIdx.x;
    int stride = gridDim.x * 128;
    // wino12: 256 floats
    for (int i = gtid; i < 256; i += stride) {
        int co = i & 7, m = (i >> 3) & 3, ci = i >> 5;
        float w0 = w12[co*24 + ci*3 + 0], w1 = w12[co*24 + ci*3 + 1], w2 = w12[co*24 + ci*3 + 2];
        dst->pack[i] = wino_w(w0, w1, w2, m);
    }
    // w21p classic: 384 floats at 256
    for (int i = gtid; i < 384; i += stride)
        dst->pack[256 + i] = w21[(i & 15) * 24 + (i >> 4)];
    // wino22: 1024 floats at 640
    for (int i = gtid; i < 1024; i += stride) {
        int co = i & 15, m = (i >> 4) & 3, ci = i >> 6;
        float w0 = w22[co*48 + ci*3 + 0], w1 = w22[co*48 + ci*3 + 1], w2 = w22[co*48 + ci*3 + 2];
        dst->pack[640 + i] = wino_w(w0, w1, w2, m);
    }
    for (int i = gtid; i < 2304; i += stride) {
        int o = i % 24; int r = i / 24;
        float w = Wl[o * 96 + (r & 15) * 6 + (r >> 4)];
        dst->linsp[i] = pk2(w, w);
    }
    if (gtid < 24) dst->linsp[LINW + gtid] = pk2(bl[gtid], bl[gtid]);
    if (gtid < 24) dst->pack[3648 + gtid] = w11[(gtid & 7) * 3 + (gtid >> 3)];
    if (gtid < 8)  dst->pack[3672 + gtid] = b11[gtid];
    if (gtid < 8)  dst->pack[3680 + gtid] = b12[gtid];
    if (gtid < 16) dst->pack[3688 + gtid] = b21[gtid];
    if (gtid < 16) dst->pack[3704 + gtid] = b22[gtid];
    if (gtid < 24) dst->pack[3720 + gtid] = bl[gtid];
}

#define P1_STRIDE 128
#define SMEM_BYTES (96 * 128 * 4)

// One full sample; __noinline__ single-copy body, called twice straight-line.
__device__ __noinline__ void process_sample(const float* __restrict__ x,
                                            float* __restrict__ p1s, int s, int n)
{
    // ---- input sample ----
    float xv[24];
    {
        const float4* xg = reinterpret_cast<const float4*>(x + (size_t)s * 24);
#pragma unroll
        for (int i = 0; i < 6; i++) {
            float4 v = xg[i];
            xv[4*i] = v.x; xv[4*i+1] = v.y; xv[4*i+2] = v.z; xv[4*i+3] = v.w;
        }
    }

    // ============ stage A: conv11 -> relu -> Winograd conv12 -> relu -> pool -> p1 ============
    float h1[4][8];                             // scalar h1 ring, 4 positions
    auto H1 = [&](int pos) {
        float xm = (pos > 0)  ? xv[pos - 1] : 0.f;
        float xc = xv[pos];
        float xp = (pos < 23) ? xv[pos + 1] : 0.f;
        float* d = h1[pos & 3];
#pragma unroll
        for (int c = 0; c < 8; c++)
            d[c] = fmaxf(fmaf(c_blob.pack[3648 + 16 + c], xp,
                         fmaf(c_blob.pack[3648 + 8 + c],  xc,
                         fmaf(c_blob.pack[3648 + c],      xm, c_blob.pack[3672 + c]))), 0.f);
    };
    H1(0); H1(1); H1(2);

#pragma unroll
    for (int t = 0; t < 12; t++) {
        // Winograd accumulators over ci: M1..M4, 4 co-pairs each. Bias rides in M2.
        u64 M1[4], M2[4], M3[4], M4[4];
        {
            uu2 b01 = cpk4(3680), b23 = cpk4(3684);
            M2[0] = b01.a; M2[1] = b01.b; M2[2] = b23.a; M2[3] = b23.b;
#pragma unroll
            for (int h = 0; h < 4; h++) { M1[h] = 0ull; M3[h] = 0ull; M4[h] = 0ull; }
        }
#pragma unroll
        for (int ci = 0; ci < 8; ci++) {
            float d0 = (t == 0)  ? 0.f : h1[(2*t - 1) & 3][ci];
            float d1 = h1[(2*t) & 3][ci];
            float d2 = h1[(2*t + 1) & 3][ci];
            float d3 = (t == 11) ? 0.f : h1[(2*t + 2) & 3][ci];
            float t1 = d0 - d2, t2v = d1 + d2, t3 = d2 - d1, t4 = d1 - d3;
            u64 T1 = pk2(t1, t1), T2 = pk2(t2v, t2v), T3 = pk2(t3, t3), T4 = pk2(t4, t4);
            int base = ci * 32;                 // wino12[(ci*4+m)*8 + co]
            uu2 w0a = cpk4(base),      w0b = cpk4(base + 4);        // m=0
            uu2 w1a = cpk4(base + 8),  w1b = cpk4(base + 12);       // m=1
            uu2 w2a = cpk4(base + 16), w2b = cpk4(base + 20);       // m=2
            uu2 w3a = cpk4(base + 24), w3b = cpk4(base + 28);       // m=3
            M1[0] = ffma2(w0a.a, T1, M1[0]); M1[1] = ffma2(w0a.b, T1, M1[1]);
            M1[2] = ffma2(w0b.a, T1, M1[2]); M1[3] = ffma2(w0b.b, T1, M1[3]);
            M2[0] = ffma2(w1a.a, T2, M2[0]); M2[1] = ffma2(w1a.b, T2, M2[1]);
            M2[2] = ffma2(w1b.a, T2, M2[2]); M2[3] = ffma2(w1b.b, T2, M2[3]);
            M3[0] = ffma2(w2a.a, T3, M3[0]); M3[1] = ffma2(w2a.b, T3, M3[1]);
            M3[2] = ffma2(w2b.a, T3, M3[2]); M3[3] = ffma2(w2b.b, T3, M3[3]);
            M4[0] = ffma2(w3a.a, T4, M4[0]); M4[1] = ffma2(w3a.b, T4, M4[1]);
            M4[2] = ffma2(w3b.a, T4, M4[2]); M4[3] = ffma2(w3b.b, T4, M4[3]);
        }
#pragma unroll
        for (int h = 0; h < 4; h++) {
            u64 y0 = add2(add2(M1[h], M2[h]), M3[h]);                 // pos 2t
            u64 y1 = add2(add2(M2[h], neg2(M3[h])), neg2(M4[h]));     // pos 2t+1
            float2 a = upk2(y0), b = upk2(y1);
            p1s[((2*h)     * 12 + t) * P1_STRIDE] = fmaxf(fmaxf(a.x, b.x), 0.f);
            p1s[((2*h + 1) * 12 + t) * P1_STRIDE] = fmaxf(fmaxf(a.y, b.y), 0.f);
        }
        if (t < 11) H1(2*t + 3);
        if (t < 10) H1(2*t + 4);
    }

    // ============ stage B: classic conv21 -> relu (ring4) -> Winograd conv22 -> pool -> p2 ====
    float r4[4][16];                            // h3 ring, 4 positions
    auto H3 = [&](int j) {                      // classic single-position conv21
        u64 D[8];
#pragma unroll
        for (int h = 0; h < 4; h++) {
            uu2 b = cpk4(3688 + 4*h);
            D[2*h] = b.a; D[2*h + 1] = b.b;
        }
#pragma unroll
        for (int ci = 0; ci < 8; ci++) {
#pragma unroll
            for (int k = 0; k < 3; k++) {
                int col = j + k - 1;
                if (col >= 0 && col <= 11) {
                    float g = p1s[(ci * 12 + col) * P1_STRIDE];
                    u64 sg = pk2(g, g);
                    int wb = 256 + (ci*3 + k) * 16;
#pragma unroll
                    for (int h = 0; h < 4; h++) {
                        uu2 w = cpk4(wb + 4*h);
                        D[2*h]     = ffma2(w.a, sg, D[2*h]);
                        D[2*h + 1] = ffma2(w.b, sg, D[2*h + 1]);
                    }
                }
            }
        }
        float* o = r4[j & 3];
#pragma unroll
        for (int p = 0; p < 8; p++) {
            float2 v = upk2(D[p]);
            o[2*p] = fmaxf(v.x, 0.f); o[2*p + 1] = fmaxf(v.y, 0.f);
        }
    };

    H3(0); H3(1); H3(2);
#pragma unroll
    for (int t2 = 0; t2 < 6; t2++) {
        // Winograd conv22 over the pair (2t2, 2t2+1), co split in two halves (reg pressure)
#pragma unroll
        for (int half = 0; half < 2; half++) {
            u64 M1[4], M2[4], M3[4], M4[4];
            {
                uu2 b0 = cpk4(3704 + half*8), b1 = cpk4(3704 + half*8 + 4);
                M2[0] = b0.a; M2[1] = b0.b; M2[2] = b1.a; M2[3] = b1.b;
#pragma unroll
                for (int h = 0; h < 4; h++) { M1[h] = 0ull; M3[h] = 0ull; M4[h] = 0ull; }
            }
#pragma unroll
            for (int ci = 0; ci < 16; ci++) {
                float d0 = (t2 == 0) ? 0.f : r4[(2*t2 - 1) & 3][ci];
                float d1 = r4[(2*t2) & 3][ci];
                float d2 = r4[(2*t2 + 1) & 3][ci];
                float d3 = (t2 == 5) ? 0.f : r4[(2*t2 + 2) & 3][ci];
                float t1 = d0 - d2, t2v = d1 + d2, t3 = d2 - d1, t4 = d1 - d3;
                u64 T1 = pk2(t1, t1), T2 = pk2(t2v, t2v), T3 = pk2(t3, t3), T4 = pk2(t4, t4);
                int base = 640 + ci * 64 + half * 8;     // wino22[(ci*4+m)*16 + co]
                uu2 w0a = cpk4(base),      w0b = cpk4(base + 4);
                uu2 w1a = cpk4(base + 16), w1b = cpk4(base + 20);
                uu2 w2a = cpk4(base + 32), w2b = cpk4(base + 36);
                uu2 w3a = cpk4(base + 48), w3b = cpk4(base + 52);
                M1[0] = ffma2(w0a.a, T1, M1[0]); M1[1] = ffma2(w0a.b, T1, M1[1]);
                M1[2] = ffma2(w0b.a, T1, M1[2]); M1[3] = ffma2(w0b.b, T1, M1[3]);
                M2[0] = ffma2(w1a.a, T2, M2[0]); M2[1] = ffma2(w1a.b, T2, M2[1]);
                M2[2] = ffma2(w1b.a, T2, M2[2]); M2[3] = ffma2(w1b.b, T2, M2[3]);
                M3[0] = ffma2(w2a.a, T3, M3[0]); M3[1] = ffma2(w2a.b, T3, M3[1]);
                M3[2] = ffma2(w2b.a, T3, M3[2]); M3[3] = ffma2(w2b.b, T3, M3[3]);
                M4[0] = ffma2(w3a.a, T4, M4[0]); M4[1] = ffma2(w3a.b, T4, M4[1]);
                M4[2] = ffma2(w3b.a, T4, M4[2]); M4[3] = ffma2(w3b.b, T4, M4[3]);
            }
#pragma unroll
            for (int h = 0; h < 4; h++) {
                u64 y0 = add2(add2(M1[h], M2[h]), M3[h]);             // pos 2t2
                u64 y1 = add2(add2(M2[h], neg2(M3[h])), neg2(M4[h])); // pos 2t2+1
                float2 a = upk2(y0), b = upk2(y1);
                int ch = half * 8 + 2*h;
                g_p2[(size_t)(t2 * 16 + ch)     * n + s] = fmaxf(fmaxf(a.x, b.x), 0.f);
                g_p2[(size_t)(t2 * 16 + ch + 1) * n + s] = fmaxf(fmaxf(a.y, b.y), 0.f);
            }
        }
        if (2*t2 + 3 <= 11) H3(2*t2 + 3);
        if (2*t2 + 4 <= 11) H3(2*t2 + 4);
    }
}

// half-grid single wave: two straight-line calls to the single-copy body.
__global__ void __launch_bounds__(128, 4)
cnn_main(const float* __restrict__ x, int n, int half)
{
    extern __shared__ float p1s_base[];
    float* p1s = p1s_base + threadIdx.x;

    int s = blockIdx.x * 128 + threadIdx.x;
    if (s >= half) return;
    process_sample(x, p1s, s, n);
    process_sample(x, p1s, s + half, n);     // half*2 >= n and s < half => s+half < n
}

// ============ linear: 2 adjacent samples per thread, samples in f32x2 lanes ==========
__global__ void __launch_bounds__(64)
lin_kernel(float* __restrict__ out, int n)
{
    int i = blockIdx.x * 64 + threadIdx.x;
    int s0 = 2 * i;
    if (s0 + 1 >= n) {                   // n even in practice; cheap guard for odd tails
        if (s0 < n) {
            float acc[24];
#pragma unroll
            for (int o = 0; o < 24; o++) acc[o] = upk2(c_blob.linsp[LINW + o]).x;
            for (int r = 0; r < 96; r++) {
                float v = g_p2[(size_t)r * n + s0];
#pragma unroll
                for (int o = 0; o < 24; o++)
                    acc[o] = fmaf(upk2(c_blob.linsp[r*24 + o]).x, v, acc[o]);
            }
#pragma unroll
            for (int o = 0; o < 24; o++) out[(size_t)s0 * 24 + o] = acc[o];
        }
        return;
    }

    u64 acc[24];
#pragma unroll
    for (int o = 0; o < 24; o++) acc[o] = c_blob.linsp[LINW + o];

#pragma unroll 8
    for (int r = 0; r < 96; r++) {
        float2 v = *reinterpret_cast<const float2*>(&g_p2[(size_t)r * n + s0]);
        u64 pv = pk2(v.x, v.y);
        const u64* w = &c_blob.linsp[r * 24];
#pragma unroll
        for (int h = 0; h < 12; h++) {
            ulonglong2 w2 = *reinterpret_cast<const ulonglong2*>(&w[2*h]);
            acc[2*h]     = ffma2(w2.x, pv, acc[2*h]);
            acc[2*h + 1] = ffma2(w2.y, pv, acc[2*h + 1]);
        }
    }
    float rA[24], rB[24];
#pragma unroll
    for (int o = 0; o < 24; o++) {
        float2 v = upk2(acc[o]);
        rA[o] = v.x; rB[o] = v.y;
    }
    float4* oA = reinterpret_cast<float4*>(out + (size_t)s0 * 24);
    float4* oB = reinterpret_cast<float4*>(out + (size_t)(s0 + 1) * 24);
#pragma unroll
    for (int q = 0; q < 6; q++) {
        oA[q] = make_float4(rA[4*q], rA[4*q+1], rA[4*q+2], rA[4*q+3]);
        oB[q] = make_float4(rB[4*q], rB[4*q+1], rB[4*q+2], rB[4*q+3]);
    }
}

extern "C" void kernel_launch(void* const* d_in, const int* in_sizes, int n_in,
                              void* d_out, int out_size)
{
    const float* x = (const float*)d_in[0];

    void* cb = nullptr;
    cudaGetSymbolAddress(&cb, c_blob);

    repack_kernel<<<32, 128>>>((Blob*)cb,
        (const float*)d_in[1], (const float*)d_in[2],
        (const float*)d_in[3], (const float*)d_in[4],
        (const float*)d_in[5], (const float*)d_in[6],
        (const float*)d_in[7], (const float*)d_in[8],
        (const float*)d_in[9], (const float*)d_in[10]);

    static bool attr_set = false;
    if (!attr_set) {
        cudaFuncSetAttribute(cnn_main,
                             cudaFuncAttributeMaxDynamicSharedMemorySize, SMEM_BYTES);
        attr_set = true;
    }

    int nSamples = in_sizes[0] / 24;            // 512*256 = 131072 (<= MAXN)
    int half = (nSamples + 1) / 2;
    int mblocks = (half + 127) / 128;           // 512 blocks -> single resident wave
    cnn_main<<<mblocks, 128, SMEM_BYTES>>>(x, nSamples, half);

    int lblocks = ((nSamples + 1) / 2 + 63) / 64;
    lin_kernel<<<lblocks, 64>>>((float*)d_out, nSamples);
}